// round 1
// baseline (speedup 1.0000x reference)
#include <cuda_runtime.h>
#include <cstdint>

// EmbeddingWithDropout:
//   out[t, :] = weight[x[t], :] * ((u[x[t]] >= 0.1) ? 1/0.9 : 0)
// x: int32 [64*2048], weight: fp32 [100000,128], u: fp32 [100000]
// out: fp32 [64*2048, 128]

#define DROPOUT 0.1f
#define INV_KEEP (1.0f / (1.0f - DROPOUT))
#define DIM_VEC 32   // 128 floats = 32 float4 per row

__global__ void __launch_bounds__(256)
emb_dropout_kernel(const int* __restrict__ x,
                   const float4* __restrict__ weight,
                   const float* __restrict__ u,
                   float4* __restrict__ out,
                   int n_tokens)
{
    // One warp per token; lane l moves float4 element l of the row.
    int gtid = blockIdx.x * blockDim.x + threadIdx.x;
    int token = gtid >> 5;
    int lane  = gtid & 31;
    if (token >= n_tokens) return;

    int idx = __ldg(x + token);
    float uu = __ldg(u + idx);
    float scale = (uu >= DROPOUT) ? INV_KEEP : 0.0f;

    float4 v = __ldg(weight + (size_t)idx * DIM_VEC + lane);
    v.x *= scale; v.y *= scale; v.z *= scale; v.w *= scale;
    out[(size_t)token * DIM_VEC + lane] = v;
}

extern "C" void kernel_launch(void* const* d_in, const int* in_sizes, int n_in,
                              void* d_out, int out_size)
{
    const int*    x      = (const int*)d_in[0];
    const float4* weight = (const float4*)d_in[1];
    const float*  u      = (const float*)d_in[2];
    float4*       out    = (float4*)d_out;

    int n_tokens = in_sizes[0];              // 64*2048 = 131072
    int threads  = 256;                      // 8 tokens per block
    int blocks   = (n_tokens * 32 + threads - 1) / threads;

    emb_dropout_kernel<<<blocks, threads>>>(x, weight, u, out, n_tokens);
}

// round 2
// speedup vs baseline: 1.5533x; 1.5533x over previous
#include <cuda_runtime.h>
#include <cstdint>

// EmbeddingWithDropout:
//   out[t, :] = weight[x[t], :] * ((u[x[t]] >= 0.1) ? 1/0.9 : 0)
// x: int32 [131072], weight: fp32 [100000,128], u: fp32 [100000]
// out: fp32 [131072, 128]

#define DROPOUT  0.1f
#define INV_KEEP (1.0f / (1.0f - DROPOUT))
#define DIM_VEC  32      // 128 floats = 32 float4 per row
#define TPW      4       // tokens per warp

__global__ void __launch_bounds__(256)
emb_dropout_kernel(const int* __restrict__ x,
                   const float4* __restrict__ weight,
                   const float* __restrict__ u,
                   float4* __restrict__ out,
                   int n_tokens)
{
    const int lane   = threadIdx.x & 31;
    const int warp_g = (blockIdx.x * (blockDim.x >> 5)) + (threadIdx.x >> 5);
    const int token0 = warp_g * TPW;
    if (token0 >= n_tokens) return;

    // Phase 1: all indices (per-warp broadcast loads, independent)
    int idx[TPW];
#pragma unroll
    for (int t = 0; t < TPW; t++)
        idx[t] = __ldg(x + token0 + t);

    // Phase 2: independent per-row uniforms (batched, MLP=TPW)
    float uu[TPW];
#pragma unroll
    for (int t = 0; t < TPW; t++)
        uu[t] = __ldg(u + idx[t]);

    // Phase 3: independent row gathers (batched, MLP=TPW, 16B/lane)
    float4 v[TPW];
#pragma unroll
    for (int t = 0; t < TPW; t++)
        v[t] = __ldg(weight + (size_t)idx[t] * DIM_VEC + lane);

    // Phase 4: scale + streaming stores (evict-first: keep table in L2)
#pragma unroll
    for (int t = 0; t < TPW; t++) {
        float s = (uu[t] >= DROPOUT) ? INV_KEEP : 0.0f;
        float4 r = v[t];
        r.x *= s; r.y *= s; r.z *= s; r.w *= s;
        __stcs(out + (size_t)(token0 + t) * DIM_VEC + lane, r);
    }
}

extern "C" void kernel_launch(void* const* d_in, const int* in_sizes, int n_in,
                              void* d_out, int out_size)
{
    const int*    x      = (const int*)d_in[0];
    const float4* weight = (const float4*)d_in[1];
    const float*  u      = (const float*)d_in[2];
    float4*       out    = (float4*)d_out;

    int n_tokens = in_sizes[0];                  // 131072
    int threads  = 256;                          // 8 warps/block
    int tokens_per_block = (threads >> 5) * TPW; // 32
    int blocks = (n_tokens + tokens_per_block - 1) / tokens_per_block;

    emb_dropout_kernel<<<blocks, threads>>>(x, weight, u, out, n_tokens);
}